// round 15
// baseline (speedup 1.0000x reference)
#include <cuda_runtime.h>
#include <cstdint>
#include <math.h>

// Problem constants (B=4, S=2048, D=1024, H=4096, E=4, K=2)
#define EXPERTS 4
#define NTOK    8192
#define DIM     1024
#define HID     4096
#define MAXROWS (2*NTOK)

#define NSTG   3
#define KSTEP  32
// per-stage smem (uint32 words): A 128x36, B 32x264 (both conflict-free)
#define A_STG  (128*36)
#define B_STG  (32*264)
#define SMEM_DYN ((NSTG*(A_STG + B_STG))*4)

// ---------------- device scratch ----------------
__device__ int      d_cnt[EXPERTS];
__device__ int      d_off[EXPERTS];
__device__ float    d_tbuf[EXPERTS*DIM];
__device__ float    d_g1[EXPERTS*HID];
__device__ float    d_mconst[EXPERTS*DIM];
__device__ float    d_csum[DIM];
__device__ int      d_btok[EXPERTS*NTOK];
__device__ float    d_bgate[EXPERTS*NTOK];
__device__ uint32_t d_xr[(size_t)NTOK*DIM];              // tf32-rounded x
__device__ uint32_t d_hact[(size_t)MAXROWS*(size_t)HID]; // tf32 bit patterns

__device__ __forceinline__ float gelu_exact(float v) {
    return 0.5f * v * (1.f + erff(v * 0.70710678118654752f));
}
__device__ __forceinline__ uint32_t f2tf(float f) {
    uint32_t r; asm("cvt.rna.tf32.f32 %0, %1;" : "=r"(r) : "f"(f)); return r;
}
__device__ __forceinline__ uint32_t smem_u32(const void* p) {
    uint32_t a;
    asm("{ .reg .u64 t; cvta.to.shared.u64 t, %1; cvt.u32.u64 %0, t; }" : "=r"(a) : "l"(p));
    return a;
}
__device__ __forceinline__ void cp16(uint32_t dst, const void* src) {
    asm volatile("cp.async.cg.shared.global [%0], [%1], 16;" :: "r"(dst), "l"(src));
}
#define CP_COMMIT() asm volatile("cp.async.commit_group;" ::: "memory")
#define CP_WAIT1()  asm volatile("cp.async.wait_group 1;" ::: "memory")

__device__ __forceinline__ void mma8(float* c, const uint32_t* a, const uint32_t* b) {
    asm volatile("mma.sync.aligned.m16n8k8.row.col.f32.tf32.tf32.f32 "
        "{%0,%1,%2,%3}, {%4,%5,%6,%7}, {%8,%9}, {%0,%1,%2,%3};"
        : "+f"(c[0]), "+f"(c[1]), "+f"(c[2]), "+f"(c[3])
        : "r"(a[0]), "r"(a[1]), "r"(a[2]), "r"(a[3]), "r"(b[0]), "r"(b[1]));
}

// fragment loaders: warp tile 64x64 = 4(mi) x 8(ni); B smem stride 264
__device__ __forceinline__ void ldA4(uint32_t a[4][4], const uint32_t* Ac,
                                     int wm, int lane, int kk) {
    #pragma unroll
    for (int mi = 0; mi < 4; mi++) {
        int r  = wm*64 + mi*16 + (lane >> 2);
        int cA = kk + (lane & 3);
        a[mi][0] = Ac[r*36 + cA];
        a[mi][1] = Ac[(r+8)*36 + cA];
        a[mi][2] = Ac[r*36 + cA + 4];
        a[mi][3] = Ac[(r+8)*36 + cA + 4];
    }
}
__device__ __forceinline__ void ldB8(uint32_t b[8][2], const uint32_t* Bc,
                                     int wn, int lane, int kk) {
    #pragma unroll
    for (int ni = 0; ni < 8; ni++) {
        int col = wn*64 + ni*8 + (lane >> 2);
        b[ni][0] = Bc[(kk + (lane & 3))*264 + col];
        b[ni][1] = Bc[(kk + 4 + (lane & 3))*264 + col];
    }
}

// ---------------- setup (fused with in-place RNA-tf32 rounding of w1) ----------------
__global__ void setup_round_w1(const float* __restrict__ b1, float* __restrict__ w1) {
    size_t i = (size_t)blockIdx.x * 256 + threadIdx.x;
    int j = (int)i;
    if (j < EXPERTS) d_cnt[j] = 0;
    if (j < EXPERTS*DIM) d_tbuf[j] = 0.f;
    if (j < EXPERTS*HID) d_g1[j] = gelu_exact(b1[j]);
    size_t o = i * 4;
    float4 v = *reinterpret_cast<const float4*>(w1 + o);
    uint4 u = make_uint4(f2tf(v.x), f2tf(v.y), f2tf(v.z), f2tf(v.w));
    *reinterpret_cast<uint4*>(w1 + o) = u;
}

__global__ void round_w2(float* __restrict__ w2) {
    size_t o = ((size_t)blockIdx.x * 256 + threadIdx.x) * 4;
    float4 v = *reinterpret_cast<const float4*>(w2 + o);
    uint4 u = make_uint4(f2tf(v.x), f2tf(v.y), f2tf(v.z), f2tf(v.w));
    *reinterpret_cast<uint4*>(w2 + o) = u;
}

__global__ void c_partial_kernel(const float* __restrict__ w2) {
    int e  = blockIdx.z;
    int d  = blockIdx.x * 256 + threadIdx.x;
    int h0 = blockIdx.y * 256;
    const float* W = w2 + ((size_t)e*HID + h0) * DIM + d;
    const float* G = d_g1 + e*HID + h0;
    float acc = 0.f;
    #pragma unroll 4
    for (int h = 0; h < 256; h++) acc += G[h] * W[(size_t)h * DIM];
    atomicAdd(&d_tbuf[e*DIM + d], acc);
}

__global__ void csum_kernel(const float* __restrict__ b2) {
    int d = blockIdx.x * 256 + threadIdx.x;
    float s = 0.f;
    #pragma unroll
    for (int e = 0; e < EXPERTS; e++) {
        float t = d_tbuf[e*DIM + d];
        d_mconst[e*DIM + d] = -t;
        s += t + b2[e*DIM + d];
    }
    d_csum[d] = s;
}

__global__ void out_init_kernel(float* __restrict__ out) {
    int i = blockIdx.x * 256 + threadIdx.x;
    out[i] = d_csum[i & (DIM - 1)];
}

// ---------------- routing: 1 warp per token; also writes tf32-rounded x ----------------
__global__ void routing_kernel(const float* __restrict__ x,
                               const float* __restrict__ wr,
                               const float* __restrict__ br) {
    int warp = (blockIdx.x * blockDim.x + threadIdx.x) >> 5;
    int lane = threadIdx.x & 31;
    if (warp >= NTOK) return;
    const float* xr = x + (size_t)warp * DIM;
    uint32_t* xo = d_xr + (size_t)warp * DIM;
    float a0 = 0.f, a1 = 0.f, a2 = 0.f, a3 = 0.f;
    for (int d = lane; d < DIM; d += 32) {
        float xv = xr[d];
        xo[d] = f2tf(xv);
        float4 w = *reinterpret_cast<const float4*>(wr + d*4);
        a0 += xv * w.x; a1 += xv * w.y; a2 += xv * w.z; a3 += xv * w.w;
    }
    #pragma unroll
    for (int o = 16; o > 0; o >>= 1) {
        a0 += __shfl_xor_sync(0xFFFFFFFFu, a0, o);
        a1 += __shfl_xor_sync(0xFFFFFFFFu, a1, o);
        a2 += __shfl_xor_sync(0xFFFFFFFFu, a2, o);
        a3 += __shfl_xor_sync(0xFFFFFFFFu, a3, o);
    }
    if (lane == 0) {
        float l0 = a0 + br[0], l1 = a1 + br[1], l2 = a2 + br[2], l3 = a3 + br[3];
        float m0 = l0; int i0 = 0;
        if (l1 > m0) { m0 = l1; i0 = 1; }
        if (l2 > m0) { m0 = l2; i0 = 2; }
        if (l3 > m0) { m0 = l3; i0 = 3; }
        float m1 = -3.4e38f; int i1 = 0;
        if (i0 != 0 && l0 > m1) { m1 = l0; i1 = 0; }
        if (i0 != 1 && l1 > m1) { m1 = l1; i1 = 1; }
        if (i0 != 2 && l2 > m1) { m1 = l2; i1 = 2; }
        if (i0 != 3 && l3 > m1) { m1 = l3; i1 = 3; }
        float ex  = expf(m1 - m0);
        float inv = 1.f / (1.f + ex);
        float g0 = inv, g1 = ex * inv;
        int p0 = atomicAdd(&d_cnt[i0], 1);
        d_btok[i0*NTOK + p0] = warp;  d_bgate[i0*NTOK + p0] = g0;
        int p1 = atomicAdd(&d_cnt[i1], 1);
        d_btok[i1*NTOK + p1] = warp;  d_bgate[i1*NTOK + p1] = g1;
    }
}

__global__ void offsets_kernel() {
    int s = 0;
    for (int e = 0; e < EXPERTS; e++) { d_off[e] = s; s += d_cnt[e]; }
}

// ======================= pipelined tf32 mma.sync GEMMs =======================
// CTA tile 128(M)x256(N)x32(K), 256 threads = 8 warps (2m x 4n) of 64x64 warp
// tiles. ST-side crossbar share halved vs 128x128 -> ceiling 73% tensor.
// 3-stage cp.async pipeline; zero cvt in loop (all operands pre-rounded).

// ---------------- GEMM1: hact = tf32(gelu(Xr[gather] @ W1_e + b1_e)) ----------------
__global__ void __launch_bounds__(256)
gemm1_kernel(const float* __restrict__ w1, const float* __restrict__ b1) {
    const int e   = blockIdx.z;
    const int cnt = d_cnt[e];
    const int mt  = blockIdx.y;
    if (mt * 128 >= cnt) return;
    const int nt  = blockIdx.x;
    const int off = d_off[e];

    extern __shared__ uint32_t sm[];
    uint32_t* As = sm;
    uint32_t* Bs = sm + NSTG*A_STG;
    const uint32_t aAddr = smem_u32(As);
    const uint32_t bAddr = smem_u32(Bs);

    const int tid  = threadIdx.x;
    const int lane = tid & 31;
    const int wid  = tid >> 5;
    const int wm   = wid & 1;     // 0..1, 64 rows
    const int wn   = wid >> 1;    // 0..3, 64 cols

    __shared__ int stok[128];
    if (tid < 128) {
        int slot = mt*128 + tid;
        stok[tid] = d_btok[e*NTOK + (slot < cnt ? slot : cnt-1)];
    }
    __syncthreads();

    const float* Bp = w1 + (size_t)e * DIM * HID + (size_t)nt * 256;
    const int arow = tid >> 3;                 // 0..31 (+i*32)
    const int ac   = (tid & 7) * 4;

    float acc[4][8][4];
    #pragma unroll
    for (int i = 0; i < 4; i++)
        #pragma unroll
        for (int j = 0; j < 8; j++)
            #pragma unroll
            for (int q = 0; q < 4; q++) acc[i][j][q] = 0.f;

    #define LOAD1(s, kt) do {                                                  \
        int k0 = (kt) * KSTEP;                                                 \
        _Pragma("unroll")                                                      \
        for (int i = 0; i < 4; i++) {                                          \
            int row = arow + i*32;                                             \
            cp16(aAddr + ((s)*A_STG + row*36 + ac)*4,                          \
                 d_xr + (size_t)stok[row]*DIM + k0 + ac);                      \
        }                                                                      \
        _Pragma("unroll")                                                      \
        for (int i = 0; i < 8; i++) {                                          \
            int idx = tid + i*256;                                             \
            int kr  = idx >> 6;                                                \
            int cc  = (idx & 63) * 4;                                          \
            cp16(bAddr + ((s)*B_STG + kr*264 + cc)*4,                          \
                 Bp + (size_t)(k0+kr)*HID + cc);                               \
        }                                                                      \
        CP_COMMIT();                                                           \
    } while (0)

    const int NIT = DIM / KSTEP;   // 32
    LOAD1(0, 0);
    LOAD1(1, 1);
    for (int i = 0; i < NIT; i++) {
        const uint32_t* Ac = As + (i % NSTG) * A_STG;
        const uint32_t* Bc = Bs + (i % NSTG) * B_STG;
        CP_WAIT1();
        __syncthreads();
        int j = i + NSTG - 1;
        if (j < NIT) LOAD1(j % NSTG, j);
        #pragma unroll
        for (int ks = 0; ks < 4; ks++) {
            uint32_t a[4][4], b[8][2];
            ldA4(a, Ac, wm, lane, ks*8);
            ldB8(b, Bc, wn, lane, ks*8);
            #pragma unroll
            for (int mi = 0; mi < 4; mi++)
                #pragma unroll
                for (int ni = 0; ni < 8; ni++)
                    mma8(acc[mi][ni], a[mi], b[ni]);
        }
    }
    #undef LOAD1

    // epilogue: +b1, gelu, tf32 bits -> d_hact
    #pragma unroll
    for (int mi = 0; mi < 4; mi++) {
        int r0 = wm*64 + mi*16 + (lane >> 2);
        #pragma unroll
        for (int half = 0; half < 2; half++) {
            int slot = mt*128 + r0 + half*8;
            if (slot >= cnt) continue;
            uint32_t* hrow = d_hact + (size_t)(off + slot) * HID;
            #pragma unroll
            for (int ni = 0; ni < 8; ni++) {
                int col = nt*256 + wn*64 + ni*8 + (lane & 3)*2;
                float v0 = acc[mi][ni][half*2+0] + __ldg(&b1[e*HID + col]);
                float v1 = acc[mi][ni][half*2+1] + __ldg(&b1[e*HID + col + 1]);
                hrow[col]   = f2tf(gelu_exact(v0));
                hrow[col+1] = f2tf(gelu_exact(v1));
            }
        }
    }
}

// ---------------- GEMM2: out[tok] += g * (H_act @ W2_e - t_e) ----------------
__global__ void __launch_bounds__(256)
gemm2_kernel(const float* __restrict__ w2, float* __restrict__ out) {
    const int e   = blockIdx.z;
    const int cnt = d_cnt[e];
    const int mt  = blockIdx.y;
    if (mt * 128 >= cnt) return;
    const int nt  = blockIdx.x;
    const int off = d_off[e];

    extern __shared__ uint32_t sm[];
    uint32_t* As = sm;
    uint32_t* Bs = sm + NSTG*A_STG;
    const uint32_t aAddr = smem_u32(As);
    const uint32_t bAddr = smem_u32(Bs);

    const int tid  = threadIdx.x;
    const int lane = tid & 31;
    const int wid  = tid >> 5;
    const int wm   = wid & 1;
    const int wn   = wid >> 1;

    const uint32_t* Ap = d_hact + (size_t)(off + mt*128) * HID;
    const float*    Bp = w2 + (size_t)e * HID * DIM + (size_t)nt * 256;
    const int arow = tid >> 3;
    const int ac   = (tid & 7) * 4;

    int rclamp[4];
    #pragma unroll
    for (int i = 0; i < 4; i++) {
        int row = arow + i*32;
        rclamp[i] = (mt*128 + row < cnt) ? row : (cnt - 1 - mt*128);
    }

    float acc[4][8][4];
    #pragma unroll
    for (int i = 0; i < 4; i++)
        #pragma unroll
        for (int j = 0; j < 8; j++)
            #pragma unroll
            for (int q = 0; q < 4; q++) acc[i][j][q] = 0.f;

    #define LOAD2(s, kt) do {                                                  \
        int k0 = (kt) * KSTEP;                                                 \
        _Pragma("unroll")                                                      \
        for (int i = 0; i < 4; i++) {                                          \
            int row = arow + i*32;                                             \
            cp16(aAddr + ((s)*A_STG + row*36 + ac)*4,                          \
                 Ap + (size_t)rclamp[i]*HID + k0 + ac);                        \
        }                                                                      \
        _Pragma("unroll")                                                      \
        for (int i = 0; i < 8; i++) {                                          \
            int idx = tid + i*256;                                             \
            int kr  = idx >> 6;                                                \
            int cc  = (idx & 63) * 4;                                          \
            cp16(bAddr + ((s)*B_STG + kr*264 + cc)*4,                          \
                 Bp + (size_t)(k0+kr)*DIM + cc);                               \
        }                                                                      \
        CP_COMMIT();                                                           \
    } while (0)

    const int NIT = HID / KSTEP;   // 128
    LOAD2(0, 0);
    LOAD2(1, 1);
    for (int i = 0; i < NIT; i++) {
        const uint32_t* Ac = As + (i % NSTG) * A_STG;
        const uint32_t* Bc = Bs + (i % NSTG) * B_STG;
        CP_WAIT1();
        __syncthreads();
        int j = i + NSTG - 1;
        if (j < NIT) LOAD2(j % NSTG, j);
        #pragma unroll
        for (int ks = 0; ks < 4; ks++) {
            uint32_t a[4][4], b[8][2];
            ldA4(a, Ac, wm, lane, ks*8);
            ldB8(b, Bc, wn, lane, ks*8);
            #pragma unroll
            for (int mi = 0; mi < 4; mi++)
                #pragma unroll
                for (int ni = 0; ni < 8; ni++)
                    mma8(acc[mi][ni], a[mi], b[ni]);
        }
    }
    #undef LOAD2

    #pragma unroll
    for (int mi = 0; mi < 4; mi++) {
        int r0 = wm*64 + mi*16 + (lane >> 2);
        #pragma unroll
        for (int ni = 0; ni < 8; ni++) {
            int col = nt*256 + wn*64 + ni*8 + (lane & 3)*2;
            float m0 = d_mconst[e*DIM + col];
            float m1 = d_mconst[e*DIM + col + 1];
            #pragma unroll
            for (int half = 0; half < 2; half++) {
                int slot = mt*128 + r0 + half*8;
                if (slot >= cnt) continue;
                int   tk = d_btok[e*NTOK + slot];
                float g  = d_bgate[e*NTOK + slot];
                float* orow = out + (size_t)tk * DIM;
                atomicAdd(&orow[col],     (acc[mi][ni][half*2+0] + m0) * g);
                atomicAdd(&orow[col + 1], (acc[mi][ni][half*2+1] + m1) * g);
            }
        }
    }
}

// ---------------- launch (gemm1 kept at profiled slot 3) ----------------
extern "C" void kernel_launch(void* const* d_in, const int* in_sizes, int n_in,
                              void* d_out, int out_size) {
    const float* x  = (const float*)d_in[0];
    float*       w1 = (float*)d_in[1];        // rounded in place (idempotent)
    const float* b1 = (const float*)d_in[2];
    float*       w2 = (float*)d_in[3];        // rounded in place (idempotent)
    const float* b2 = (const float*)d_in[4];
    const float* wr = (const float*)d_in[5];
    const float* br = (const float*)d_in[6];
    float* out = (float*)d_out;

    cudaFuncSetAttribute(gemm1_kernel, cudaFuncAttributeMaxDynamicSharedMemorySize, SMEM_DYN);
    cudaFuncSetAttribute(gemm2_kernel, cudaFuncAttributeMaxDynamicSharedMemorySize, SMEM_DYN);

    setup_round_w1<<<(EXPERTS*DIM*HID/4)/256, 256>>>(b1, w1);                // 0
    routing_kernel<<<(NTOK*32)/256, 256>>>(x, wr, br);                       // 1
    offsets_kernel<<<1, 1>>>();                                              // 2
    gemm1_kernel<<<dim3(HID/256, NTOK/128, EXPERTS), 256, SMEM_DYN>>>(w1, b1); // 3 <- ncu
    round_w2<<<(EXPERTS*HID*DIM/4)/256, 256>>>(w2);                          // 4
    c_partial_kernel<<<dim3(DIM/256, HID/256, EXPERTS), 256>>>(w2);          // 5
    csum_kernel<<<DIM/256, 256>>>(b2);                                       // 6
    out_init_kernel<<<(NTOK*DIM)/256, 256>>>(out);                           // 7
    gemm2_kernel<<<dim3(DIM/256, NTOK/128, EXPERTS), 256, SMEM_DYN>>>(w2, out);   // 8
}

// round 16
// speedup vs baseline: 1.1193x; 1.1193x over previous
#include <cuda_runtime.h>
#include <cstdint>
#include <math.h>

// Problem constants (B=4, S=2048, D=1024, H=4096, E=4, K=2)
#define EXPERTS 4
#define NTOK    8192
#define DIM     1024
#define HID     4096
#define MAXROWS (2*NTOK)

#define NSTG   2
#define KSTEP  32
// per-stage smem (uint32 words): A 128x36, B 32x136 (both conflict-free)
#define A_STG  (128*36)
#define B_STG  (32*136)
#define SMEM_DYN ((NSTG*(A_STG + B_STG))*4)   // 71680 B -> 3 CTAs/SM

// ---------------- device scratch ----------------
__device__ int      d_cnt[EXPERTS];
__device__ int      d_off[EXPERTS];
__device__ float    d_tbuf[EXPERTS*DIM];
__device__ float    d_g1[EXPERTS*HID];
__device__ float    d_mconst[EXPERTS*DIM];
__device__ float    d_csum[DIM];
__device__ int      d_btok[EXPERTS*NTOK];
__device__ float    d_bgate[EXPERTS*NTOK];
__device__ uint32_t d_xr[(size_t)NTOK*DIM];              // tf32-rounded x
__device__ uint32_t d_hact[(size_t)MAXROWS*(size_t)HID]; // tf32 bit patterns

__device__ __forceinline__ float gelu_exact(float v) {
    return 0.5f * v * (1.f + erff(v * 0.70710678118654752f));
}
__device__ __forceinline__ uint32_t f2tf(float f) {
    uint32_t r; asm("cvt.rna.tf32.f32 %0, %1;" : "=r"(r) : "f"(f)); return r;
}
__device__ __forceinline__ uint32_t smem_u32(const void* p) {
    uint32_t a;
    asm("{ .reg .u64 t; cvta.to.shared.u64 t, %1; cvt.u32.u64 %0, t; }" : "=r"(a) : "l"(p));
    return a;
}
__device__ __forceinline__ void cp16(uint32_t dst, const void* src) {
    asm volatile("cp.async.cg.shared.global [%0], [%1], 16;" :: "r"(dst), "l"(src));
}
#define CP_COMMIT() asm volatile("cp.async.commit_group;" ::: "memory")
#define CP_WAIT0()  asm volatile("cp.async.wait_group 0;" ::: "memory")

__device__ __forceinline__ void mma8(float* c, const uint32_t* a, const uint32_t* b) {
    asm volatile("mma.sync.aligned.m16n8k8.row.col.f32.tf32.tf32.f32 "
        "{%0,%1,%2,%3}, {%4,%5,%6,%7}, {%8,%9}, {%0,%1,%2,%3};"
        : "+f"(c[0]), "+f"(c[1]), "+f"(c[2]), "+f"(c[3])
        : "r"(a[0]), "r"(a[1]), "r"(a[2]), "r"(a[3]), "r"(b[0]), "r"(b[1]));
}

// fragment loaders: warp tile 64x64 = 4(mi) x 8(ni)
__device__ __forceinline__ void ldA4(uint32_t a[4][4], const uint32_t* Ac,
                                     int wm, int lane, int kk) {
    #pragma unroll
    for (int mi = 0; mi < 4; mi++) {
        int r  = wm*64 + mi*16 + (lane >> 2);
        int cA = kk + (lane & 3);
        a[mi][0] = Ac[r*36 + cA];
        a[mi][1] = Ac[(r+8)*36 + cA];
        a[mi][2] = Ac[r*36 + cA + 4];
        a[mi][3] = Ac[(r+8)*36 + cA + 4];
    }
}
__device__ __forceinline__ void ldB8(uint32_t b[8][2], const uint32_t* Bc,
                                     int wn, int lane, int kk) {
    #pragma unroll
    for (int ni = 0; ni < 8; ni++) {
        int col = wn*64 + ni*8 + (lane >> 2);
        b[ni][0] = Bc[(kk + (lane & 3))*136 + col];
        b[ni][1] = Bc[(kk + 4 + (lane & 3))*136 + col];
    }
}

// ---------------- setup (fused with in-place RNA-tf32 rounding of w1) ----------------
__global__ void setup_round_w1(const float* __restrict__ b1, float* __restrict__ w1) {
    size_t i = (size_t)blockIdx.x * 256 + threadIdx.x;
    int j = (int)i;
    if (j < EXPERTS) d_cnt[j] = 0;
    if (j < EXPERTS*DIM) d_tbuf[j] = 0.f;
    if (j < EXPERTS*HID) d_g1[j] = gelu_exact(b1[j]);
    size_t o = i * 4;
    float4 v = *reinterpret_cast<const float4*>(w1 + o);
    uint4 u = make_uint4(f2tf(v.x), f2tf(v.y), f2tf(v.z), f2tf(v.w));
    *reinterpret_cast<uint4*>(w1 + o) = u;
}

__global__ void round_w2(float* __restrict__ w2) {
    size_t o = ((size_t)blockIdx.x * 256 + threadIdx.x) * 4;
    float4 v = *reinterpret_cast<const float4*>(w2 + o);
    uint4 u = make_uint4(f2tf(v.x), f2tf(v.y), f2tf(v.z), f2tf(v.w));
    *reinterpret_cast<uint4*>(w2 + o) = u;
}

__global__ void c_partial_kernel(const float* __restrict__ w2) {
    int e  = blockIdx.z;
    int d  = blockIdx.x * 256 + threadIdx.x;
    int h0 = blockIdx.y * 256;
    const float* W = w2 + ((size_t)e*HID + h0) * DIM + d;
    const float* G = d_g1 + e*HID + h0;
    float acc = 0.f;
    #pragma unroll 4
    for (int h = 0; h < 256; h++) acc += G[h] * W[(size_t)h * DIM];
    atomicAdd(&d_tbuf[e*DIM + d], acc);
}

__global__ void csum_kernel(const float* __restrict__ b2) {
    int d = blockIdx.x * 256 + threadIdx.x;
    float s = 0.f;
    #pragma unroll
    for (int e = 0; e < EXPERTS; e++) {
        float t = d_tbuf[e*DIM + d];
        d_mconst[e*DIM + d] = -t;
        s += t + b2[e*DIM + d];
    }
    d_csum[d] = s;
}

__global__ void out_init_kernel(float* __restrict__ out) {
    int i = blockIdx.x * 256 + threadIdx.x;
    out[i] = d_csum[i & (DIM - 1)];
}

// ---------------- routing: 1 warp per token; also writes tf32-rounded x ----------------
__global__ void routing_kernel(const float* __restrict__ x,
                               const float* __restrict__ wr,
                               const float* __restrict__ br) {
    int warp = (blockIdx.x * blockDim.x + threadIdx.x) >> 5;
    int lane = threadIdx.x & 31;
    if (warp >= NTOK) return;
    const float* xr = x + (size_t)warp * DIM;
    uint32_t* xo = d_xr + (size_t)warp * DIM;
    float a0 = 0.f, a1 = 0.f, a2 = 0.f, a3 = 0.f;
    for (int d = lane; d < DIM; d += 32) {
        float xv = xr[d];
        xo[d] = f2tf(xv);
        float4 w = *reinterpret_cast<const float4*>(wr + d*4);
        a0 += xv * w.x; a1 += xv * w.y; a2 += xv * w.z; a3 += xv * w.w;
    }
    #pragma unroll
    for (int o = 16; o > 0; o >>= 1) {
        a0 += __shfl_xor_sync(0xFFFFFFFFu, a0, o);
        a1 += __shfl_xor_sync(0xFFFFFFFFu, a1, o);
        a2 += __shfl_xor_sync(0xFFFFFFFFu, a2, o);
        a3 += __shfl_xor_sync(0xFFFFFFFFu, a3, o);
    }
    if (lane == 0) {
        float l0 = a0 + br[0], l1 = a1 + br[1], l2 = a2 + br[2], l3 = a3 + br[3];
        float m0 = l0; int i0 = 0;
        if (l1 > m0) { m0 = l1; i0 = 1; }
        if (l2 > m0) { m0 = l2; i0 = 2; }
        if (l3 > m0) { m0 = l3; i0 = 3; }
        float m1 = -3.4e38f; int i1 = 0;
        if (i0 != 0 && l0 > m1) { m1 = l0; i1 = 0; }
        if (i0 != 1 && l1 > m1) { m1 = l1; i1 = 1; }
        if (i0 != 2 && l2 > m1) { m1 = l2; i1 = 2; }
        if (i0 != 3 && l3 > m1) { m1 = l3; i1 = 3; }
        float ex  = expf(m1 - m0);
        float inv = 1.f / (1.f + ex);
        float g0 = inv, g1 = ex * inv;
        int p0 = atomicAdd(&d_cnt[i0], 1);
        d_btok[i0*NTOK + p0] = warp;  d_bgate[i0*NTOK + p0] = g0;
        int p1 = atomicAdd(&d_cnt[i1], 1);
        d_btok[i1*NTOK + p1] = warp;  d_bgate[i1*NTOK + p1] = g1;
    }
}

__global__ void offsets_kernel() {
    int s = 0;
    for (int e = 0; e < EXPERTS; e++) { d_off[e] = s; s += d_cnt[e]; }
}

// ======================= pipelined tf32 mma.sync GEMMs =======================
// CTA tile 128x128x32, 128 threads = 4 warps (2m x 2n) of 64x64 warp tiles.
// NSTG=2 double buffer -> 71.7KB smem -> 3 CTAs/SM (12 warps) for cross-CTA
// overlap (R15 showed co-residency dominates ST-share). Zero cvt in loop.

// ---------------- GEMM1: hact = tf32(gelu(Xr[gather] @ W1_e + b1_e)) ----------------
__global__ void __launch_bounds__(128, 3)
gemm1_kernel(const float* __restrict__ w1, const float* __restrict__ b1) {
    const int e   = blockIdx.z;
    const int cnt = d_cnt[e];
    const int mt  = blockIdx.y;
    if (mt * 128 >= cnt) return;
    const int nt  = blockIdx.x;
    const int off = d_off[e];

    extern __shared__ uint32_t sm[];
    uint32_t* As = sm;
    uint32_t* Bs = sm + NSTG*A_STG;
    const uint32_t aAddr = smem_u32(As);
    const uint32_t bAddr = smem_u32(Bs);

    const int tid  = threadIdx.x;
    const int lane = tid & 31;
    const int wid  = tid >> 5;
    const int wm   = wid & 1;     // 0..1, 64 rows
    const int wn   = wid >> 1;    // 0..1, 64 cols

    __shared__ int stok[128];
    {
        int slot = mt*128 + tid;
        stok[tid] = d_btok[e*NTOK + (slot < cnt ? slot : cnt-1)];
    }
    __syncthreads();

    const float* Bp = w1 + (size_t)e * DIM * HID + (size_t)nt * 128;
    const int arow = tid >> 3;                 // 0..15 (+i*16)
    const int ac   = (tid & 7) * 4;

    float acc[4][8][4];
    #pragma unroll
    for (int i = 0; i < 4; i++)
        #pragma unroll
        for (int j = 0; j < 8; j++)
            #pragma unroll
            for (int q = 0; q < 4; q++) acc[i][j][q] = 0.f;

    #define LOAD1(s, kt) do {                                                  \
        int k0 = (kt) * KSTEP;                                                 \
        _Pragma("unroll")                                                      \
        for (int i = 0; i < 8; i++) {                                          \
            int row = arow + i*16;                                             \
            cp16(aAddr + ((s)*A_STG + row*36 + ac)*4,                          \
                 d_xr + (size_t)stok[row]*DIM + k0 + ac);                      \
        }                                                                      \
        _Pragma("unroll")                                                      \
        for (int i = 0; i < 8; i++) {                                          \
            int idx = tid + i*128;                                             \
            int kr  = idx >> 5;                                                \
            int cc  = (idx & 31) * 4;                                          \
            cp16(bAddr + ((s)*B_STG + kr*136 + cc)*4,                          \
                 Bp + (size_t)(k0+kr)*HID + cc);                               \
        }                                                                      \
        CP_COMMIT();                                                           \
    } while (0)

    const int NIT = DIM / KSTEP;   // 32
    LOAD1(0, 0);
    for (int i = 0; i < NIT; i++) {
        const uint32_t* Ac = As + (i & 1) * A_STG;
        const uint32_t* Bc = Bs + (i & 1) * B_STG;
        CP_WAIT0();
        __syncthreads();
        int j = i + 1;
        if (j < NIT) LOAD1(j & 1, j);
        #pragma unroll
        for (int ks = 0; ks < 4; ks++) {
            uint32_t a[4][4], b[8][2];
            ldA4(a, Ac, wm, lane, ks*8);
            ldB8(b, Bc, wn, lane, ks*8);
            #pragma unroll
            for (int mi = 0; mi < 4; mi++)
                #pragma unroll
                for (int ni = 0; ni < 8; ni++)
                    mma8(acc[mi][ni], a[mi], b[ni]);
        }
    }
    #undef LOAD1

    // epilogue: +b1, gelu, tf32 bits -> d_hact
    #pragma unroll
    for (int mi = 0; mi < 4; mi++) {
        int r0 = wm*64 + mi*16 + (lane >> 2);
        #pragma unroll
        for (int half = 0; half < 2; half++) {
            int slot = mt*128 + r0 + half*8;
            if (slot >= cnt) continue;
            uint32_t* hrow = d_hact + (size_t)(off + slot) * HID;
            #pragma unroll
            for (int ni = 0; ni < 8; ni++) {
                int col = nt*128 + wn*64 + ni*8 + (lane & 3)*2;
                float v0 = acc[mi][ni][half*2+0] + __ldg(&b1[e*HID + col]);
                float v1 = acc[mi][ni][half*2+1] + __ldg(&b1[e*HID + col + 1]);
                hrow[col]   = f2tf(gelu_exact(v0));
                hrow[col+1] = f2tf(gelu_exact(v1));
            }
        }
    }
}

// ---------------- GEMM2: out[tok] += g * (H_act @ W2_e - t_e) ----------------
__global__ void __launch_bounds__(128, 3)
gemm2_kernel(const float* __restrict__ w2, float* __restrict__ out) {
    const int e   = blockIdx.z;
    const int cnt = d_cnt[e];
    const int mt  = blockIdx.y;
    if (mt * 128 >= cnt) return;
    const int nt  = blockIdx.x;
    const int off = d_off[e];

    extern __shared__ uint32_t sm[];
    uint32_t* As = sm;
    uint32_t* Bs = sm + NSTG*A_STG;
    const uint32_t aAddr = smem_u32(As);
    const uint32_t bAddr = smem_u32(Bs);

    const int tid  = threadIdx.x;
    const int lane = tid & 31;
    const int wid  = tid >> 5;
    const int wm   = wid & 1;
    const int wn   = wid >> 1;

    const uint32_t* Ap = d_hact + (size_t)(off + mt*128) * HID;
    const float*    Bp = w2 + (size_t)e * HID * DIM + (size_t)nt * 128;
    const int arow = tid >> 3;
    const int ac   = (tid & 7) * 4;

    int rclamp[8];
    #pragma unroll
    for (int i = 0; i < 8; i++) {
        int row = arow + i*16;
        rclamp[i] = (mt*128 + row < cnt) ? row : (cnt - 1 - mt*128);
    }

    float acc[4][8][4];
    #pragma unroll
    for (int i = 0; i < 4; i++)
        #pragma unroll
        for (int j = 0; j < 8; j++)
            #pragma unroll
            for (int q = 0; q < 4; q++) acc[i][j][q] = 0.f;

    #define LOAD2(s, kt) do {                                                  \
        int k0 = (kt) * KSTEP;                                                 \
        _Pragma("unroll")                                                      \
        for (int i = 0; i < 8; i++) {                                          \
            int row = arow + i*16;                                             \
            cp16(aAddr + ((s)*A_STG + row*36 + ac)*4,                          \
                 Ap + (size_t)rclamp[i]*HID + k0 + ac);                        \
        }                                                                      \
        _Pragma("unroll")                                                      \
        for (int i = 0; i < 8; i++) {                                          \
            int idx = tid + i*128;                                             \
            int kr  = idx >> 5;                                                \
            int cc  = (idx & 31) * 4;                                          \
            cp16(bAddr + ((s)*B_STG + kr*136 + cc)*4,                          \
                 Bp + (size_t)(k0+kr)*DIM + cc);                               \
        }                                                                      \
        CP_COMMIT();                                                           \
    } while (0)

    const int NIT = HID / KSTEP;   // 128
    LOAD2(0, 0);
    for (int i = 0; i < NIT; i++) {
        const uint32_t* Ac = As + (i & 1) * A_STG;
        const uint32_t* Bc = Bs + (i & 1) * B_STG;
        CP_WAIT0();
        __syncthreads();
        int j = i + 1;
        if (j < NIT) LOAD2(j & 1, j);
        #pragma unroll
        for (int ks = 0; ks < 4; ks++) {
            uint32_t a[4][4], b[8][2];
            ldA4(a, Ac, wm, lane, ks*8);
            ldB8(b, Bc, wn, lane, ks*8);
            #pragma unroll
            for (int mi = 0; mi < 4; mi++)
                #pragma unroll
                for (int ni = 0; ni < 8; ni++)
                    mma8(acc[mi][ni], a[mi], b[ni]);
        }
    }
    #undef LOAD2

    #pragma unroll
    for (int mi = 0; mi < 4; mi++) {
        int r0 = wm*64 + mi*16 + (lane >> 2);
        #pragma unroll
        for (int ni = 0; ni < 8; ni++) {
            int col = nt*128 + wn*64 + ni*8 + (lane & 3)*2;
            float m0 = d_mconst[e*DIM + col];
            float m1 = d_mconst[e*DIM + col + 1];
            #pragma unroll
            for (int half = 0; half < 2; half++) {
                int slot = mt*128 + r0 + half*8;
                if (slot >= cnt) continue;
                int   tk = d_btok[e*NTOK + slot];
                float g  = d_bgate[e*NTOK + slot];
                float* orow = out + (size_t)tk * DIM;
                atomicAdd(&orow[col],     (acc[mi][ni][half*2+0] + m0) * g);
                atomicAdd(&orow[col + 1], (acc[mi][ni][half*2+1] + m1) * g);
            }
        }
    }
}

// ---------------- launch (gemm1 kept at profiled slot 3) ----------------
extern "C" void kernel_launch(void* const* d_in, const int* in_sizes, int n_in,
                              void* d_out, int out_size) {
    const float* x  = (const float*)d_in[0];
    float*       w1 = (float*)d_in[1];        // rounded in place (idempotent)
    const float* b1 = (const float*)d_in[2];
    float*       w2 = (float*)d_in[3];        // rounded in place (idempotent)
    const float* b2 = (const float*)d_in[4];
    const float* wr = (const float*)d_in[5];
    const float* br = (const float*)d_in[6];
    float* out = (float*)d_out;

    cudaFuncSetAttribute(gemm1_kernel, cudaFuncAttributeMaxDynamicSharedMemorySize, SMEM_DYN);
    cudaFuncSetAttribute(gemm2_kernel, cudaFuncAttributeMaxDynamicSharedMemorySize, SMEM_DYN);

    setup_round_w1<<<(EXPERTS*DIM*HID/4)/256, 256>>>(b1, w1);                // 0
    routing_kernel<<<(NTOK*32)/256, 256>>>(x, wr, br);                       // 1
    offsets_kernel<<<1, 1>>>();                                              // 2
    gemm1_kernel<<<dim3(HID/128, NTOK/128, EXPERTS), 128, SMEM_DYN>>>(w1, b1); // 3 <- ncu
    round_w2<<<(EXPERTS*HID*DIM/4)/256, 256>>>(w2);                          // 4
    c_partial_kernel<<<dim3(DIM/256, HID/256, EXPERTS), 256>>>(w2);          // 5
    csum_kernel<<<DIM/256, 256>>>(b2);                                       // 6
    out_init_kernel<<<(NTOK*DIM)/256, 256>>>(out);                           // 7
    gemm2_kernel<<<dim3(DIM/128, NTOK/128, EXPERTS), 128, SMEM_DYN>>>(w2, out);   // 8
}